// round 5
// baseline (speedup 1.0000x reference)
#include <cuda_runtime.h>
#include <cstdint>
#include <math.h>

// Problem constants
#define BATCH 64
#define M     4096   // NPROP (columns)
#define NGTC  128    // max GT (rows)
#define NT    512    // threads per CTA
#define CPT   (M/NT) // 8 columns per thread
#define NW    (NT/32)

__global__ __launch_bounds__(NT, 1)
void matcher_kernel(const int*   __restrict__ nag,   // [B]
                    const float* __restrict__ gtn,   // [B][NGT][3]
                    const float* __restrict__ qn,    // [M][3]
                    float*       __restrict__ out)   // [2][B][M] : inds then mask
{
    const int b    = blockIdx.x;
    const int tid  = threadIdx.x;
    const int lane = tid & 31;
    const int wid  = tid >> 5;

    __shared__ short          p[M + 1];       // column -> matched row (1-based), 0 = free
    __shared__ unsigned short way[M + 1];     // Dijkstra predecessor column
    __shared__ double         u[NGTC + 1];    // row duals (1-based), DOUBLE like reference
    __shared__ float          gns[NGTC * 3];  // gt normals for this batch
    __shared__ double         wredv[NW];      // per-warp min value
    __shared__ int            wredj[NW];      // per-warp argmin column
    __shared__ double         bval;           // broadcast delta
    __shared__ int            bj1;            // broadcast argmin column

    const int k = nag[b];

    // ---- init shared state ----
    for (int j = tid; j <= M; j += NT) p[j] = 0;
    for (int j = tid; j <= NGTC; j += NT) u[j] = 0.0;
    for (int j = tid; j < k * 3; j += NT) gns[j] = gtn[(size_t)b * NGTC * 3 + j];

    // ---- per-thread register state (8 columns, strided by NT) ----
    float  q0[CPT], q1[CPT], q2[CPT];
    double v[CPT], minv[CPT];
    #pragma unroll
    for (int t = 0; t < CPT; t++) {
        int c = tid + t * NT;
        q0[t] = qn[c * 3 + 0];
        q1[t] = qn[c * 3 + 1];
        q2[t] = qn[c * 3 + 2];
        v[t]  = 0.0;
    }
    __syncthreads();

    const double DINF = 1e300;

    // ---- JV shortest augmenting path, one row at a time ----
    for (int i = 1; i <= k; i++) {
        unsigned usedmask = 0;
        #pragma unroll
        for (int t = 0; t < CPT; t++) minv[t] = DINF;
        if (tid == 0) p[0] = (short)i;
        __syncthreads();

        int j0 = 0;
        while (true) {
            const int    i0  = p[j0];        // uniform
            const double ui0 = u[i0];        // uniform

            // mark column j0 used (register bitmask on owning thread)
            if (j0 > 0) {
                int c = j0 - 1;
                if ((c & (NT - 1)) == tid) usedmask |= 1u << (c >> 9); // c / NT
            }

            const float gx = gns[(i0 - 1) * 3 + 0];
            const float gy = gns[(i0 - 1) * 3 + 1];
            const float gz = gns[(i0 - 1) * 3 + 2];

            // relax free columns; track local argmin (double value, smallest j on tie)
            double best  = DINF;
            int    bestj = M + 1;
            #pragma unroll
            for (int t = 0; t < CPT; t++) {
                if (!((usedmask >> t) & 1u)) {
                    int   j   = tid + t * NT + 1;
                    // fp32 cost entry (matches reference C), widened for dual arithmetic
                    float dot = q0[t] * gx;
                    dot = fmaf(q1[t], gy, dot);
                    dot = fmaf(q2[t], gz, dot);
                    float  cf  = 1.0f - dot;
                    double cur = (double)cf - ui0 - v[t];
                    if (cur < minv[t]) { minv[t] = cur; way[j] = (unsigned short)j0; }
                    // per-thread columns are in ascending j as t grows, so strict <
                    // keeps the smallest j among exact ties
                    if (minv[t] < best) { best = minv[t]; bestj = j; }
                }
            }
            // warp argmin on (value, index)
            #pragma unroll
            for (int off = 16; off; off >>= 1) {
                double ov = __shfl_down_sync(0xFFFFFFFFu, best,  off);
                int    oj = __shfl_down_sync(0xFFFFFFFFu, bestj, off);
                if (ov < best || (ov == best && oj < bestj)) { best = ov; bestj = oj; }
            }
            if (lane == 0) { wredv[wid] = best; wredj[wid] = bestj; }
            __syncthreads();
            if (wid == 0) {
                double bv = (lane < NW) ? wredv[lane] : DINF;
                int    bj = (lane < NW) ? wredj[lane] : (M + 1);
                #pragma unroll
                for (int off = 8; off; off >>= 1) {
                    double ov = __shfl_down_sync(0xFFFFFFFFu, bv, off);
                    int    oj = __shfl_down_sync(0xFFFFFFFFu, bj, off);
                    if (ov < bv || (ov == bv && oj < bj)) { bv = ov; bj = oj; }
                }
                if (lane == 0) { bval = bv; bj1 = bj; }
            }
            __syncthreads();

            const double delta = bval;
            const int    j1    = bj1;

            // dual updates (all in double, like reference)
            #pragma unroll
            for (int t = 0; t < CPT; t++) {
                if ((usedmask >> t) & 1u) {
                    v[t] -= delta;
                    int j = tid + t * NT + 1;
                    int r = p[j];                 // distinct rows across used cols
                    u[r] += delta;
                } else {
                    minv[t] -= delta;
                }
            }
            if (tid == 0) u[i] += delta;          // virtual column j=0, p[0]=i

            const int pmatch = p[j1];             // read before any p writes
            __syncthreads();                      // u/way updates visible
            j0 = j1;
            if (pmatch == 0) break;
        }

        // augment along 'way' path (serial, short)
        if (tid == 0) {
            int jj = j0;
            while (jj != 0) {
                int jp = way[jj];
                p[jj] = p[jp];
                jj = jp;
            }
        }
        __syncthreads();
    }

    // ---- write outputs: [0] per_prop_gt_inds, [1] proposal_matched_mask ----
    float* outInds = out + (size_t)b * M;
    float* outMask = out + (size_t)BATCH * M + (size_t)b * M;
    #pragma unroll
    for (int t = 0; t < CPT; t++) {
        int c = tid + t * NT;
        int r = p[c + 1];
        outInds[c] = (r > 0) ? (float)(r - 1) : 0.0f;
        outMask[c] = (r > 0) ? 1.0f : 0.0f;
    }
}

extern "C" void kernel_launch(void* const* d_in, const int* in_sizes, int n_in,
                              void* d_out, int out_size) {
    // metadata order: cls_prob[0], gt_box_present[1], num_actual_gt[2],
    //                 gt_normal_normalized[3], query_normals[4]
    const int*   nag = (const int*)  d_in[2];
    const float* gtn = (const float*)d_in[3];
    const float* qn  = (const float*)d_in[4];
    matcher_kernel<<<BATCH, NT>>>(nag, gtn, qn, (float*)d_out);
}

// round 6
// speedup vs baseline: 1.0033x; 1.0033x over previous
#include <cuda_runtime.h>
#include <cstdint>
#include <math.h>

// Problem constants
#define BATCH 64
#define M     4096   // NPROP (columns)
#define NGTC  128    // max GT (rows)
#define NT    512    // threads per CTA
#define CPT   (M/NT) // 8 columns per thread
#define NW    (NT/32)

__global__ __launch_bounds__(NT, 1)
void matcher_kernel(const int*   __restrict__ nag,   // [B]
                    const float* __restrict__ gtn,   // [B][NGT][3]
                    const float* __restrict__ qn,    // [M][3]
                    float*       __restrict__ out)   // [2][B][M] : inds then mask
{
    const int b    = blockIdx.x;
    const int tid  = threadIdx.x;
    const int lane = tid & 31;
    const int wid  = tid >> 5;

    __shared__ short          p[M + 1];       // column -> matched row (1-based), 0 = free
    __shared__ unsigned short way[M + 1];     // Dijkstra predecessor column
    __shared__ double         u[NGTC + 1];    // row duals (1-based), DOUBLE like reference
    __shared__ float          gns[NGTC * 3];  // gt normals for this batch
    __shared__ double         wredv[NW];      // per-warp min value
    __shared__ int            wredj[NW];      // per-warp argmin column
    __shared__ double         bval;           // broadcast delta
    __shared__ int            bj1;            // broadcast argmin column

    const int k = nag[b];

    // ---- init shared state ----
    for (int j = tid; j <= M; j += NT) p[j] = 0;
    for (int j = tid; j <= NGTC; j += NT) u[j] = 0.0;
    for (int j = tid; j < k * 3; j += NT) gns[j] = gtn[(size_t)b * NGTC * 3 + j];

    // ---- per-thread register state (8 columns, strided by NT) ----
    float  q0[CPT], q1[CPT], q2[CPT];
    double v[CPT], minv[CPT];
    #pragma unroll
    for (int t = 0; t < CPT; t++) {
        int c = tid + t * NT;
        q0[t] = qn[c * 3 + 0];
        q1[t] = qn[c * 3 + 1];
        q2[t] = qn[c * 3 + 2];
        v[t]  = 0.0;
    }
    __syncthreads();

    const double DINF = 1e300;

    // ---- JV shortest augmenting path, one row at a time ----
    for (int i = 1; i <= k; i++) {
        unsigned usedmask = 0;
        #pragma unroll
        for (int t = 0; t < CPT; t++) minv[t] = DINF;
        if (tid == 0) p[0] = (short)i;
        __syncthreads();

        int j0 = 0;
        while (true) {
            const int    i0  = p[j0];        // uniform
            const double ui0 = u[i0];        // uniform

            // mark column j0 used (register bitmask on owning thread)
            if (j0 > 0) {
                int c = j0 - 1;
                if ((c & (NT - 1)) == tid) usedmask |= 1u << (c >> 9); // c / NT
            }

            const float gx = gns[(i0 - 1) * 3 + 0];
            const float gy = gns[(i0 - 1) * 3 + 1];
            const float gz = gns[(i0 - 1) * 3 + 2];

            // relax free columns; track local argmin (double value, smallest j on tie)
            double best  = DINF;
            int    bestj = M + 1;
            #pragma unroll
            for (int t = 0; t < CPT; t++) {
                if (!((usedmask >> t) & 1u)) {
                    int   j   = tid + t * NT + 1;
                    // fp32 cost entry (matches reference C), widened for dual arithmetic
                    float dot = q0[t] * gx;
                    dot = fmaf(q1[t], gy, dot);
                    dot = fmaf(q2[t], gz, dot);
                    float  cf  = 1.0f - dot;
                    double cur = (double)cf - ui0 - v[t];
                    if (cur < minv[t]) { minv[t] = cur; way[j] = (unsigned short)j0; }
                    // per-thread columns are in ascending j as t grows, so strict <
                    // keeps the smallest j among exact ties
                    if (minv[t] < best) { best = minv[t]; bestj = j; }
                }
            }
            // warp argmin on (value, index)
            #pragma unroll
            for (int off = 16; off; off >>= 1) {
                double ov = __shfl_down_sync(0xFFFFFFFFu, best,  off);
                int    oj = __shfl_down_sync(0xFFFFFFFFu, bestj, off);
                if (ov < best || (ov == best && oj < bestj)) { best = ov; bestj = oj; }
            }
            if (lane == 0) { wredv[wid] = best; wredj[wid] = bestj; }
            __syncthreads();
            if (wid == 0) {
                double bv = (lane < NW) ? wredv[lane] : DINF;
                int    bj = (lane < NW) ? wredj[lane] : (M + 1);
                #pragma unroll
                for (int off = 8; off; off >>= 1) {
                    double ov = __shfl_down_sync(0xFFFFFFFFu, bv, off);
                    int    oj = __shfl_down_sync(0xFFFFFFFFu, bj, off);
                    if (ov < bv || (ov == bv && oj < bj)) { bv = ov; bj = oj; }
                }
                if (lane == 0) { bval = bv; bj1 = bj; }
            }
            __syncthreads();

            const double delta = bval;
            const int    j1    = bj1;

            // dual updates (all in double, like reference)
            #pragma unroll
            for (int t = 0; t < CPT; t++) {
                if ((usedmask >> t) & 1u) {
                    v[t] -= delta;
                    int j = tid + t * NT + 1;
                    int r = p[j];                 // distinct rows across used cols
                    u[r] += delta;
                } else {
                    minv[t] -= delta;
                }
            }
            if (tid == 0) u[i] += delta;          // virtual column j=0, p[0]=i

            const int pmatch = p[j1];             // read before any p writes
            __syncthreads();                      // u/way updates visible
            j0 = j1;
            if (pmatch == 0) break;
        }

        // augment along 'way' path (serial, short)
        if (tid == 0) {
            int jj = j0;
            while (jj != 0) {
                int jp = way[jj];
                p[jj] = p[jp];
                jj = jp;
            }
        }
        __syncthreads();
    }

    // ---- write outputs: [0] per_prop_gt_inds, [1] proposal_matched_mask ----
    float* outInds = out + (size_t)b * M;
    float* outMask = out + (size_t)BATCH * M + (size_t)b * M;
    #pragma unroll
    for (int t = 0; t < CPT; t++) {
        int c = tid + t * NT;
        int r = p[c + 1];
        outInds[c] = (r > 0) ? (float)(r - 1) : 0.0f;
        outMask[c] = (r > 0) ? 1.0f : 0.0f;
    }
}

extern "C" void kernel_launch(void* const* d_in, const int* in_sizes, int n_in,
                              void* d_out, int out_size) {
    // metadata order: cls_prob[0], gt_box_present[1], num_actual_gt[2],
    //                 gt_normal_normalized[3], query_normals[4]
    const int*   nag = (const int*)  d_in[2];
    const float* gtn = (const float*)d_in[3];
    const float* qn  = (const float*)d_in[4];
    matcher_kernel<<<BATCH, NT>>>(nag, gtn, qn, (float*)d_out);
}

// round 7
// speedup vs baseline: 1.0634x; 1.0599x over previous
#include <cuda_runtime.h>
#include <cstdint>

// Problem constants
#define BATCH 64
#define M     4096   // NPROP (columns)
#define NGTC  128    // max GT (rows)
#define NT    512    // threads per CTA
#define CPT   (M/NT) // 8 columns per thread
#define NW    (NT/32)

__global__ __launch_bounds__(NT, 1)
void matcher_kernel(const int*   __restrict__ nag,   // [B]
                    const float* __restrict__ gtn,   // [B][NGT][3]
                    const float* __restrict__ qn,    // [M][3]
                    float*       __restrict__ out)   // [2][B][M] : inds then mask
{
    const int b    = blockIdx.x;
    const int tid  = threadIdx.x;
    const int lane = tid & 31;
    const int wid  = tid >> 5;

    __shared__ short          p[M + 1];       // column -> matched row (1-based), 0 = free
    __shared__ unsigned short way[M + 1];     // predecessor column (0 = from cur_row)
    __shared__ double         u[NGTC + 1];    // row duals (1-based)
    __shared__ float          gns[NGTC * 3];  // gt normals for this batch
    __shared__ double         wredv[2][NW];   // per-warp min value (parity-buffered)
    __shared__ int            wredj[2][NW];   // per-warp argmin column

    const int k = nag[b];

    // ---- init shared state ----
    for (int j = tid; j <= M; j += NT) p[j] = 0;
    for (int j = tid; j <= NGTC; j += NT) u[j] = 0.0;
    for (int j = tid; j < k * 3; j += NT) gns[j] = gtn[(size_t)b * NGTC * 3 + j];

    // ---- per-thread register state (8 columns, strided by NT) ----
    float  q0[CPT], q1[CPT], q2[CPT];
    double v[CPT], d[CPT];   // column duals + absolute shortest-path costs
    #pragma unroll
    for (int t = 0; t < CPT; t++) {
        int c = tid + t * NT;
        q0[t] = qn[c * 3 + 0];
        q1[t] = qn[c * 3 + 1];
        q2[t] = qn[c * 3 + 2];
        v[t]  = 0.0;
    }
    __syncthreads();

    const double DINF = 1e300;
    int par = 0;   // parity for double-buffered reduction scratch

    // ---- LAPJV shortest augmenting path, one row per phase ----
    for (int i = 1; i <= k; i++) {
        unsigned usedmask = 0;
        #pragma unroll
        for (int t = 0; t < CPT; t++) d[t] = DINF;

        int    i0 = i, j0 = 0, jend = 0;
        double minVal = 0.0;

        while (true) {
            // uniform per-step scalars (u constant during phase)
            const double h1 = minVal - u[i0] + 1.0;   // fold the "1 - dot" constant in
            const float  gx = gns[(i0 - 1) * 3 + 0];
            const float  gy = gns[(i0 - 1) * 3 + 1];
            const float  gz = gns[(i0 - 1) * 3 + 2];

            // relax free columns; track local argmin of absolute d (smallest j on tie)
            double best  = DINF;
            int    bestj = M + 1;
            #pragma unroll
            for (int t = 0; t < CPT; t++) {
                if (!((usedmask >> t) & 1u)) {
                    int   j   = tid + t * NT + 1;
                    float dot = q0[t] * gx;
                    dot = fmaf(q1[t], gy, dot);
                    dot = fmaf(q2[t], gz, dot);
                    double r = (h1 - v[t]) - (double)dot;   // minVal + (1-dot) - u[i0] - v[j]
                    if (r < d[t]) { d[t] = r; way[j] = (unsigned short)j0; }
                    if (d[t] < best) { best = d[t]; bestj = j; }
                }
            }
            // warp argmin
            #pragma unroll
            for (int off = 16; off; off >>= 1) {
                double ov = __shfl_down_sync(0xFFFFFFFFu, best,  off);
                int    oj = __shfl_down_sync(0xFFFFFFFFu, bestj, off);
                if (ov < best || (ov == best && oj < bestj)) { best = ov; bestj = oj; }
            }
            if (lane == 0) { wredv[par][wid] = best; wredj[par][wid] = bestj; }
            __syncthreads();   // the ONLY barrier in the step

            // every warp reduces the 16 partials redundantly (no 2nd barrier needed;
            // parity buffer prevents write-after-read across steps)
            double bv = (lane < NW) ? wredv[par][lane] : DINF;
            int    bj = (lane < NW) ? wredj[par][lane] : (M + 1);
            #pragma unroll
            for (int off = 8; off; off >>= 1) {
                double ov = __shfl_down_sync(0xFFFFFFFFu, bv, off);
                int    oj = __shfl_down_sync(0xFFFFFFFFu, bj, off);
                if (ov < bv || (ov == bv && oj < bj)) { bv = ov; bj = oj; }
            }
            minVal = __shfl_sync(0xFFFFFFFFu, bv, 0);
            const int j1 = __shfl_sync(0xFFFFFFFFu, bj, 0);
            par ^= 1;

            const int pmatch = p[j1];        // p stable during phase
            if (pmatch == 0) { jend = j1; break; }

            // mark j1 scanned (register bitmask on owning thread)
            { int c = j1 - 1; if ((c & (NT - 1)) == tid) usedmask |= 1u << (c >> 9); }
            i0 = pmatch;
            j0 = j1;
        }

        // ---- phase-end dual updates (scanned set only), BEFORE augmentation ----
        #pragma unroll
        for (int t = 0; t < CPT; t++) {
            if ((usedmask >> t) & 1u) {
                double adj = minVal - d[t];
                v[t] -= adj;                         // v[j] -= minVal - d[j]
                int j = tid + t * NT + 1;
                u[p[j]] += adj;                      // distinct rows across scanned cols
            }
        }
        if (tid == 0) u[i] += minVal;
        __syncthreads();                             // u writes + p/way reads done

        if (tid == 0) {                              // augment along predecessor chain
            int j = jend;
            while (true) {
                int jp = way[j];
                if (jp == 0) { p[j] = (short)i; break; }
                p[j] = p[jp];
                j = jp;
            }
        }
        __syncthreads();                             // p/way stable before next phase
    }

    // ---- write outputs: [0] per_prop_gt_inds, [1] proposal_matched_mask ----
    float* outInds = out + (size_t)b * M;
    float* outMask = out + (size_t)BATCH * M + (size_t)b * M;
    #pragma unroll
    for (int t = 0; t < CPT; t++) {
        int c = tid + t * NT;
        int r = p[c + 1];
        outInds[c] = (r > 0) ? (float)(r - 1) : 0.0f;
        outMask[c] = (r > 0) ? 1.0f : 0.0f;
    }
}

extern "C" void kernel_launch(void* const* d_in, const int* in_sizes, int n_in,
                              void* d_out, int out_size) {
    // metadata order: cls_prob[0], gt_box_present[1], num_actual_gt[2],
    //                 gt_normal_normalized[3], query_normals[4]
    const int*   nag = (const int*)  d_in[2];
    const float* gtn = (const float*)d_in[3];
    const float* qn  = (const float*)d_in[4];
    matcher_kernel<<<BATCH, NT>>>(nag, gtn, qn, (float*)d_out);
}